// round 3
// baseline (speedup 1.0000x reference)
#include <cuda_runtime.h>
#include <math.h>
#include <float.h>

#define BN 4096
#define BATCH 2

// ---------------- scratch (device globals; no allocation allowed) ----------------
__device__ __align__(16) float g_f0n[BATCH * BN * 64];
__device__ __align__(16) float g_f1n[BATCH * BN * 64];
__device__ __align__(16) float g_K[(size_t)BATCH * BN * BN];        // 134 MB
__device__ float  g_colpart[32 * BATCH * BN];                        // per row-tile partial col sums
__device__ __align__(16) float4 g_pb[BATCH * BN];                    // (b, b*x, b*y, b*z)
__device__ float  g_flow[BATCH * BN * 3];
__device__ int    g_idx[BATCH * BN * 32];
__device__ __align__(16) float g_x1[BATCH * BN * 32];
__device__ __align__(16) float g_x2[BATCH * BN * 64];
__device__ __align__(16) float g_x3[BATCH * BN * 128];

// ---------------- helpers ----------------
static __device__ __forceinline__ float fast_exp(float x) {
    // exp(x) for x in [-95, 1]; 2^t poly deg-5, |rel err| < 3e-6
    float y  = x * 1.4426950408889634f;
    float fn = rintf(y);
    int   ei = (int)fn;
    float t  = y - fn;
    float p  = 1.3333558146e-3f;
    p = fmaf(p, t, 9.6181291076e-3f);
    p = fmaf(p, t, 5.5504108665e-2f);
    p = fmaf(p, t, 2.4022650696e-1f);
    p = fmaf(p, t, 6.9314718056e-1f);
    p = fmaf(p, t, 1.0f);
    return p * __int_as_float((ei + 127) << 23);
}

static __device__ __forceinline__ float lrelu(float x) { return fmaxf(x, 0.1f * x); }

// ---------------- feature L2 normalization (one warp per row) ----------------
__global__ void norm_kernel(const float* __restrict__ fin, float* __restrict__ fout) {
    int row  = blockIdx.x * 8 + (threadIdx.x >> 5);
    int lane = threadIdx.x & 31;
    const float* p = fin + (size_t)row * 64;
    float v0 = p[lane], v1 = p[lane + 32];
    float s = v0 * v0 + v1 * v1;
    #pragma unroll
    for (int o = 16; o; o >>= 1) s += __shfl_xor_sync(0xffffffffu, s, o);
    float inv = 1.0f / sqrtf(s + 1e-8f);
    float* q = fout + (size_t)row * 64;
    q[lane] = v0 * inv;
    q[lane + 32] = v1 * inv;
}

// ---------------- pass 1: K = exp((dot-1)/eps)*support, + column partial sums ----------------
// 128x128 tile, 256 threads, 8x8 micro-tile. K=64 split into two 32-chunks so
// smem stays static (2 * 32*132 * 4 B = 33.8 KB) -> no dynamic-smem attribute,
// ~2x block residency vs the 66 KB variant.
__global__ void pass1_kernel(const float* __restrict__ pc0, const float* __restrict__ pc1,
                             const float* __restrict__ epsp) {
    __shared__ float As[32 * 132];   // [c][row], pad 4
    __shared__ float Bs[32 * 132];
    int b  = blockIdx.z;
    int n0 = blockIdx.y * 128;
    int m0 = blockIdx.x * 128;
    int t  = threadIdx.x;

    int tc = t & 15, tr = t >> 4;     // 16x16 thread grid of 8x8 micro-tiles
    int rb = tr * 8, cb2 = tc * 8;
    float acc[8][8];
    #pragma unroll
    for (int i = 0; i < 8; i++)
        #pragma unroll
        for (int j = 0; j < 8; j++) acc[i][j] = 0.0f;

    int lrow  = t >> 1;               // 0..127
    int lhalf = (t & 1) * 16;         // which 16-channel half of the 32-chunk

    #pragma unroll
    for (int kc = 0; kc < 2; kc++) {
        // load + transpose 128x32 chunk of each tile into smem
        const float4* srcA = (const float4*)(g_f0n + ((size_t)(b * BN + n0 + lrow)) * 64 + kc * 32 + lhalf);
        const float4* srcB = (const float4*)(g_f1n + ((size_t)(b * BN + m0 + lrow)) * 64 + kc * 32 + lhalf);
        #pragma unroll
        for (int k = 0; k < 4; k++) {
            float4 v = srcA[k];
            int c = lhalf + k * 4;
            As[(c + 0) * 132 + lrow] = v.x; As[(c + 1) * 132 + lrow] = v.y;
            As[(c + 2) * 132 + lrow] = v.z; As[(c + 3) * 132 + lrow] = v.w;
            float4 u = srcB[k];
            Bs[(c + 0) * 132 + lrow] = u.x; Bs[(c + 1) * 132 + lrow] = u.y;
            Bs[(c + 2) * 132 + lrow] = u.z; Bs[(c + 3) * 132 + lrow] = u.w;
        }
        __syncthreads();

        #pragma unroll 4
        for (int c = 0; c < 32; c++) {
            float4 x0 = *(const float4*)&As[c * 132 + rb];
            float4 x1 = *(const float4*)&As[c * 132 + rb + 4];
            float4 y0 = *(const float4*)&Bs[c * 132 + cb2];
            float4 y1 = *(const float4*)&Bs[c * 132 + cb2 + 4];
            float av[8] = {x0.x, x0.y, x0.z, x0.w, x1.x, x1.y, x1.z, x1.w};
            float bv[8] = {y0.x, y0.y, y0.z, y0.w, y1.x, y1.y, y1.z, y1.w};
            #pragma unroll
            for (int i = 0; i < 8; i++)
                #pragma unroll
                for (int j = 0; j < 8; j++) acc[i][j] = fmaf(av[i], bv[j], acc[i][j]);
        }
        __syncthreads();
    }

    float eps = expf(epsp[0]) + 0.025f;
    float inv_eps = 1.0f / eps;

    float p1x[8], p1y[8], p1z[8];
    #pragma unroll
    for (int j = 0; j < 8; j++) {
        int mb_ = (b * BN + m0 + cb2 + j) * 3;
        p1x[j] = pc1[mb_]; p1y[j] = pc1[mb_ + 1]; p1z[j] = pc1[mb_ + 2];
    }

    float colp[8] = {0, 0, 0, 0, 0, 0, 0, 0};
    #pragma unroll
    for (int i = 0; i < 8; i++) {
        int nb_ = (b * BN + n0 + rb + i) * 3;
        float p0x = pc0[nb_], p0y = pc0[nb_ + 1], p0z = pc0[nb_ + 2];
        #pragma unroll
        for (int j = 0; j < 8; j++) {
            float dx = p0x - p1x[j], dy = p0y - p1y[j], dz = p0z - p1z[j];
            float d  = dx * dx + dy * dy + dz * dz;
            float kv = (d < 100.0f) ? fast_exp((acc[i][j] - 1.0f) * inv_eps) : 0.0f;
            acc[i][j] = kv;
            colp[j] += kv;
        }
        size_t off = ((size_t)(b * BN) + n0 + rb + i) * BN + m0 + cb2;
        *(float4*)(g_K + off)     = make_float4(acc[i][0], acc[i][1], acc[i][2], acc[i][3]);
        *(float4*)(g_K + off + 4) = make_float4(acc[i][4], acc[i][5], acc[i][6], acc[i][7]);
    }

    // reduce 16 partial col-sums per column through smem (deterministic)
    #pragma unroll
    for (int j = 0; j < 8; j++) As[tr * 132 + cb2 + j] = colp[j];
    __syncthreads();
    if (t < 128) {
        float s = 0.0f;
        #pragma unroll
        for (int k = 0; k < 16; k++) s += As[k * 132 + t];
        g_colpart[blockIdx.y * (BATCH * BN) + b * BN + m0 + t] = s;
    }
}

// ---------------- b-vector + packed (b, b*pc1) table ----------------
__global__ void bvec_kernel(const float* __restrict__ pc1,
                            const float* __restrict__ gamp, const float* __restrict__ epsp) {
    int t = blockIdx.x * blockDim.x + threadIdx.x;
    if (t >= BATCH * BN) return;
    float cs = 0.0f;
    #pragma unroll 8
    for (int k = 0; k < 32; k++) cs += g_colpart[k * (BATCH * BN) + t];
    float eps = expf(epsp[0]) + 0.025f;
    float gam = expf(gamp[0]);
    float power = gam / (gam + eps);
    float KTa = cs * (1.0f / (float)BN);
    float bv = powf((1.0f / (float)BN) / (KTa + 1e-8f), power);
    float x = pc1[t * 3 + 0], y = pc1[t * 3 + 1], z = pc1[t * 3 + 2];
    g_pb[t] = make_float4(bv, bv * x, bv * y, bv * z);
}

// ---------------- pass 2: row reductions -> ot_flow (one warp per row) ----------------
__global__ void pass2_kernel(const float* __restrict__ pc0,
                             const float* __restrict__ gamp, const float* __restrict__ epsp) {
    int warp = threadIdx.x >> 5, lane = threadIdx.x & 31;
    int b = blockIdx.y;
    int n = blockIdx.x * 8 + warp;
    const float4* Kr = (const float4*)(g_K + ((size_t)(b * BN + n)) * BN);
    const float4* pb = (const float4*)(g_pb + b * BN);
    float sb = 0.f, sx = 0.f, sy = 0.f, sz = 0.f;
    for (int mc = lane; mc < BN / 4; mc += 32) {
        float4 k4 = __ldcs(&Kr[mc]);                  // stream K, don't thrash L1
        float4 q0 = __ldg(&pb[4 * mc + 0]);
        float4 q1 = __ldg(&pb[4 * mc + 1]);
        float4 q2 = __ldg(&pb[4 * mc + 2]);
        float4 q3 = __ldg(&pb[4 * mc + 3]);
        sb = fmaf(k4.x, q0.x, sb); sx = fmaf(k4.x, q0.y, sx); sy = fmaf(k4.x, q0.z, sy); sz = fmaf(k4.x, q0.w, sz);
        sb = fmaf(k4.y, q1.x, sb); sx = fmaf(k4.y, q1.y, sx); sy = fmaf(k4.y, q1.z, sy); sz = fmaf(k4.y, q1.w, sz);
        sb = fmaf(k4.z, q2.x, sb); sx = fmaf(k4.z, q2.y, sx); sy = fmaf(k4.z, q2.z, sy); sz = fmaf(k4.z, q2.w, sz);
        sb = fmaf(k4.w, q3.x, sb); sx = fmaf(k4.w, q3.y, sx); sy = fmaf(k4.w, q3.z, sy); sz = fmaf(k4.w, q3.w, sz);
    }
    #pragma unroll
    for (int o = 16; o; o >>= 1) {
        sb += __shfl_xor_sync(0xffffffffu, sb, o);
        sx += __shfl_xor_sync(0xffffffffu, sx, o);
        sy += __shfl_xor_sync(0xffffffffu, sy, o);
        sz += __shfl_xor_sync(0xffffffffu, sz, o);
    }
    if (lane == 0) {
        float eps = expf(epsp[0]) + 0.025f;
        float gam = expf(gamp[0]);
        float power = gam / (gam + eps);
        float a = powf((1.0f / (float)BN) / (sb + 1e-8f), power);
        float invd = 1.0f / (a * sb + 1e-8f);
        int base = (b * BN + n) * 3;
        g_flow[base + 0] = a * sx * invd - pc0[base + 0];
        g_flow[base + 1] = a * sy * invd - pc0[base + 1];
        g_flow[base + 2] = a * sz * invd - pc0[base + 2];
    }
}

// ---------------- KNN: thread-per-point, 32-slot replace-max list ----------------
__global__ void knn_kernel(const float* __restrict__ pc0) {
    __shared__ float sx[256], sy[256], sz[256], sq[256];
    int b = blockIdx.y;
    int n = blockIdx.x * 256 + threadIdx.x;
    int nb_ = (b * BN + n) * 3;
    float px = pc0[nb_], py = pc0[nb_ + 1], pz = pc0[nb_ + 2];
    float pn2 = px * px + py * py + pz * pz;
    float nd[32]; int ni[32];
    #pragma unroll
    for (int i = 0; i < 32; i++) { nd[i] = FLT_MAX; ni[i] = 0; }
    float worst = FLT_MAX; int wpos = 0;
    for (int t0 = 0; t0 < BN; t0 += 256) {
        __syncthreads();
        int m = t0 + threadIdx.x;
        int mb_ = (b * BN + m) * 3;
        float qx = pc0[mb_], qy = pc0[mb_ + 1], qz = pc0[mb_ + 2];
        sx[threadIdx.x] = qx; sy[threadIdx.x] = qy; sz[threadIdx.x] = qz;
        sq[threadIdx.x] = qx * qx + qy * qy + qz * qz;
        __syncthreads();
        for (int j = 0; j < 256; j++) {
            float d = pn2 + sq[j] - 2.0f * (px * sx[j] + py * sy[j] + pz * sz[j]);
            if (d < worst) {
                nd[wpos] = d; ni[wpos] = t0 + j;
                worst = nd[0]; wpos = 0;
                for (int i = 1; i < 32; i++)
                    if (nd[i] > worst) { worst = nd[i]; wpos = i; }
            }
        }
    }
    int base = (b * BN + n) * 32;
    for (int i = 0; i < 32; i++) g_idx[base + i] = ni[i];
}

// ---------------- set convolution (block per point, thread per out channel) ----------------
template <int CIN, int COUT>
__global__ void setconv_kernel(const float* __restrict__ fin, const float* __restrict__ pc0,
                               const float* __restrict__ w1, const float* __restrict__ b1,
                               const float* __restrict__ w2, const float* __restrict__ b2,
                               const float* __restrict__ w3, const float* __restrict__ b3,
                               float* __restrict__ fout) {
    __shared__ __align__(16) float sfeat[32 * CIN];
    __shared__ float sedge[32 * 3];
    __shared__ int   sidx[32];
    __shared__ float sh[COUT];
    int pid = blockIdx.x;
    int b = pid >> 12, n = pid & 4095;
    int j = threadIdx.x;
    if (j < 32) sidx[j] = g_idx[pid * 32 + j];
    __syncthreads();
    for (int q = j; q < 32 * CIN; q += COUT) {
        int l = q / CIN, c = q - l * CIN;
        sfeat[q] = fin[((size_t)(b * BN) + sidx[l]) * CIN + c];
    }
    if (j < 32) {
        int m = sidx[j];
        int mb_ = (b * BN + m) * 3, nb_ = (b * BN + n) * 3;
        sedge[j * 3 + 0] = pc0[mb_ + 0] - pc0[nb_ + 0];
        sedge[j * 3 + 1] = pc0[mb_ + 1] - pc0[nb_ + 1];
        sedge[j * 3 + 2] = pc0[mb_ + 2] - pc0[nb_ + 2];
    }
    __syncthreads();

    float w[CIN + 3];
    #pragma unroll
    for (int i = 0; i < CIN + 3; i++) w[i] = w1[i * COUT + j];   // hoisted weight column
    float bias = b1[j];
    float mx = -FLT_MAX;
    for (int l = 0; l < 32; l++) {
        float acc = bias;
        if constexpr (CIN % 4 == 0) {
            const float4* sf4 = (const float4*)&sfeat[l * CIN];
            #pragma unroll
            for (int i = 0; i < CIN / 4; i++) {
                float4 v = sf4[i];
                acc = fmaf(v.x, w[4 * i + 0], acc);
                acc = fmaf(v.y, w[4 * i + 1], acc);
                acc = fmaf(v.z, w[4 * i + 2], acc);
                acc = fmaf(v.w, w[4 * i + 3], acc);
            }
        } else {
            #pragma unroll
            for (int i = 0; i < CIN; i++) acc = fmaf(sfeat[l * CIN + i], w[i], acc);
        }
        acc = fmaf(sedge[l * 3 + 0], w[CIN + 0], acc);
        acc = fmaf(sedge[l * 3 + 1], w[CIN + 1], acc);
        acc = fmaf(sedge[l * 3 + 2], w[CIN + 2], acc);
        mx = fmaxf(mx, lrelu(acc));
    }
    sh[j] = mx;
    __syncthreads();
    float acc2 = b2[j];
    #pragma unroll 4
    for (int i = 0; i < COUT; i++) acc2 = fmaf(sh[i], w2[i * COUT + j], acc2);
    acc2 = lrelu(acc2);
    __syncthreads();
    sh[j] = acc2;
    __syncthreads();
    float acc3 = b3[j];
    #pragma unroll 4
    for (int i = 0; i < COUT; i++) acc3 = fmaf(sh[i], w3[i * COUT + j], acc3);
    fout[(size_t)pid * COUT + j] = lrelu(acc3);
}

// ---------------- final: out = ot_flow + x3 @ wfc + bfc ----------------
__global__ void final_kernel(const float* __restrict__ wfc, const float* __restrict__ bfc,
                             float* __restrict__ out) {
    int t = blockIdx.x * blockDim.x + threadIdx.x;
    if (t >= BATCH * BN * 3) return;
    int pid = t / 3, d = t - pid * 3;
    float acc = bfc[d];
    const float* xr = g_x3 + (size_t)pid * 128;
    #pragma unroll 8
    for (int i = 0; i < 128; i++) acc = fmaf(xr[i], wfc[i * 3 + d], acc);
    out[t] = g_flow[t] + acc;
}

// ---------------- launch ----------------
extern "C" void kernel_launch(void* const* d_in, const int* in_sizes, int n_in,
                              void* d_out, int out_size) {
    const float* pc0     = (const float*)d_in[0];
    const float* pc1     = (const float*)d_in[1];
    const float* feats0  = (const float*)d_in[2];
    const float* feats1  = (const float*)d_in[3];
    const float* gamma   = (const float*)d_in[4];
    const float* epsilon = (const float*)d_in[5];
    const float* w1_1 = (const float*)d_in[6];  const float* b1_1 = (const float*)d_in[7];
    const float* w1_2 = (const float*)d_in[8];  const float* b1_2 = (const float*)d_in[9];
    const float* w1_3 = (const float*)d_in[10]; const float* b1_3 = (const float*)d_in[11];
    const float* w2_1 = (const float*)d_in[12]; const float* b2_1 = (const float*)d_in[13];
    const float* w2_2 = (const float*)d_in[14]; const float* b2_2 = (const float*)d_in[15];
    const float* w2_3 = (const float*)d_in[16]; const float* b2_3 = (const float*)d_in[17];
    const float* w3_1 = (const float*)d_in[18]; const float* b3_1 = (const float*)d_in[19];
    const float* w3_2 = (const float*)d_in[20]; const float* b3_2 = (const float*)d_in[21];
    const float* w3_3 = (const float*)d_in[22]; const float* b3_3 = (const float*)d_in[23];
    const float* wfc  = (const float*)d_in[24]; const float* bfc  = (const float*)d_in[25];
    float* out = (float*)d_out;

    void *p_f0n, *p_f1n, *p_flow, *p_x1, *p_x2, *p_x3;
    cudaGetSymbolAddress(&p_f0n,  g_f0n);
    cudaGetSymbolAddress(&p_f1n,  g_f1n);
    cudaGetSymbolAddress(&p_flow, g_flow);
    cudaGetSymbolAddress(&p_x1,   g_x1);
    cudaGetSymbolAddress(&p_x2,   g_x2);
    cudaGetSymbolAddress(&p_x3,   g_x3);

    norm_kernel<<<1024, 256>>>(feats0, (float*)p_f0n);
    norm_kernel<<<1024, 256>>>(feats1, (float*)p_f1n);
    pass1_kernel<<<dim3(32, 32, 2), 256>>>(pc0, pc1, epsilon);
    bvec_kernel<<<32, 256>>>(pc1, gamma, epsilon);
    pass2_kernel<<<dim3(512, 2), 256>>>(pc0, gamma, epsilon);
    knn_kernel<<<dim3(16, 2), 256>>>(pc0);
    setconv_kernel<3, 32><<<BATCH * BN, 32>>>((const float*)p_flow, pc0,
        w1_1, b1_1, w1_2, b1_2, w1_3, b1_3, (float*)p_x1);
    setconv_kernel<32, 64><<<BATCH * BN, 64>>>((const float*)p_x1, pc0,
        w2_1, b2_1, w2_2, b2_2, w2_3, b2_3, (float*)p_x2);
    setconv_kernel<64, 128><<<BATCH * BN, 128>>>((const float*)p_x2, pc0,
        w3_1, b3_1, w3_2, b3_2, w3_3, b3_3, (float*)p_x3);
    final_kernel<<<(BATCH * BN * 3 + 255) / 256, 256>>>(wfc, bfc, out);
}

// round 4
// speedup vs baseline: 1.7781x; 1.7781x over previous
#include <cuda_runtime.h>
#include <math.h>
#include <float.h>

#define BN 4096
#define BATCH 2

// ---------------- scratch (device globals; no allocation allowed) ----------------
__device__ __align__(16) float g_f0n[BATCH * BN * 64];
__device__ __align__(16) float g_f1n[BATCH * BN * 64];
__device__ __align__(16) float g_K[(size_t)BATCH * BN * BN];        // 134 MB
__device__ float  g_colpart[32 * BATCH * BN];                        // per row-tile partial col sums
__device__ __align__(16) float4 g_pb[BATCH * BN];                    // (b, b*x, b*y, b*z)
__device__ float  g_flow[BATCH * BN * 3];
__device__ int    g_idx[BATCH * BN * 32];
__device__ __align__(16) float g_x1[BATCH * BN * 32];
__device__ __align__(16) float g_x2[BATCH * BN * 64];
__device__ __align__(16) float g_x3[BATCH * BN * 128];

// ---------------- helpers ----------------
static __device__ __forceinline__ float fast_exp(float x) {
    // exp(x) for x in [-95, 1]; 2^t poly deg-5, |rel err| < 3e-6
    float y  = x * 1.4426950408889634f;
    float fn = rintf(y);
    int   ei = (int)fn;
    float t  = y - fn;
    float p  = 1.3333558146e-3f;
    p = fmaf(p, t, 9.6181291076e-3f);
    p = fmaf(p, t, 5.5504108665e-2f);
    p = fmaf(p, t, 2.4022650696e-1f);
    p = fmaf(p, t, 6.9314718056e-1f);
    p = fmaf(p, t, 1.0f);
    return p * __int_as_float((ei + 127) << 23);
}

static __device__ __forceinline__ float lrelu(float x) { return fmaxf(x, 0.1f * x); }

// ---------------- feature L2 normalization (one warp per row) ----------------
__global__ void norm_kernel(const float* __restrict__ fin, float* __restrict__ fout) {
    int row  = blockIdx.x * 8 + (threadIdx.x >> 5);
    int lane = threadIdx.x & 31;
    const float* p = fin + (size_t)row * 64;
    float v0 = p[lane], v1 = p[lane + 32];
    float s = v0 * v0 + v1 * v1;
    #pragma unroll
    for (int o = 16; o; o >>= 1) s += __shfl_xor_sync(0xffffffffu, s, o);
    float inv = 1.0f / sqrtf(s + 1e-8f);
    float* q = fout + (size_t)row * 64;
    q[lane] = v0 * inv;
    q[lane + 32] = v1 * inv;
}

// ---------------- KNN: 4 threads per point, smem 32-lists, 2-level max hierarchy ------
#define KT 128   // threads per block; 32 points per block, 4 threads each

struct KnnState {
    float worst;
    int   wslot;
};

// smem arrays are passed as raw pointers; layout is [slot][KT] (thread-major: conflict-free)
static __device__ __forceinline__ void knn_insert(
    float d, int j, int tid,
    float* s_nd, int* s_ni, float* s_gm, int* s_gp, KnnState& st)
{
    // replace the current worst slot
    s_nd[st.wslot * KT + tid] = d;
    s_ni[st.wslot * KT + tid] = j;
    int g = st.wslot >> 3;
    // rescan group g (8 slots) for its max + position
    const float* base = s_nd + (g * 8) * KT + tid;
    float bm = base[0]; int bp = 0;
    #pragma unroll
    for (int q = 1; q < 8; q++) {
        float v = base[q * KT];
        if (v > bm) { bm = v; bp = q; }
    }
    s_gm[g * KT + tid] = bm;
    s_gp[g * KT + tid] = g * 8 + bp;
    // recombine 4 group maxes
    float w = s_gm[0 * KT + tid]; int wg = 0;
    #pragma unroll
    for (int g2 = 1; g2 < 4; g2++) {
        float v = s_gm[g2 * KT + tid];
        if (v > w) { w = v; wg = g2; }
    }
    st.worst = w;
    st.wslot = s_gp[wg * KT + tid];
}

__global__ void knn_kernel(const float* __restrict__ pc0) {
    __shared__ float t_x[256], t_y[256], t_z[256], t_q[256];
    __shared__ float s_nd[32 * KT];
    __shared__ int   s_ni[32 * KT];
    __shared__ float s_gm[4 * KT];
    __shared__ int   s_gp[4 * KT];

    int b   = blockIdx.y;
    int tid = threadIdx.x;
    int p   = blockIdx.x * (KT / 4) + (tid >> 2);   // point index within batch
    int r   = tid & 3;                               // candidate residue class

    int nb = (b * BN + p) * 3;
    float px = pc0[nb], py = pc0[nb + 1], pz = pc0[nb + 2];
    float pn2 = px * px + py * py + pz * pz;

    #pragma unroll
    for (int i = 0; i < 32; i++) { s_nd[i * KT + tid] = FLT_MAX; s_ni[i * KT + tid] = 0; }
    #pragma unroll
    for (int g = 0; g < 4; g++) { s_gm[g * KT + tid] = FLT_MAX; s_gp[g * KT + tid] = g * 8; }
    KnnState st; st.worst = FLT_MAX; st.wslot = 0;

    for (int t0 = 0; t0 < BN; t0 += 256) {
        __syncthreads();
        #pragma unroll
        for (int u = 0; u < 2; u++) {
            int m  = t0 + tid + u * KT;
            int mb = (b * BN + m) * 3;
            float qx = pc0[mb], qy = pc0[mb + 1], qz = pc0[mb + 2];
            t_x[tid + u * KT] = qx; t_y[tid + u * KT] = qy; t_z[tid + u * KT] = qz;
            t_q[tid + u * KT] = qx * qx + qy * qy + qz * qz;
        }
        __syncthreads();
        #pragma unroll 4
        for (int k = 0; k < 64; k++) {
            int jj = 4 * k + r;
            float d = pn2 + t_q[jj] - 2.0f * (px * t_x[jj] + py * t_y[jj] + pz * t_z[jj]);
            if (d < st.worst)
                knn_insert(d, t0 + jj, tid, s_nd, s_ni, s_gm, s_gp, st);
        }
    }
    __syncthreads();

    // leader (r==0) merges the other 3 partial lists into its own
    if (r == 0) {
        #pragma unroll
        for (int rr = 1; rr < 4; rr++) {
            #pragma unroll 4
            for (int i = 0; i < 32; i++) {
                float d = s_nd[i * KT + tid + rr];
                if (d < st.worst) {
                    int j = s_ni[i * KT + tid + rr];
                    knn_insert(d, j, tid, s_nd, s_ni, s_gm, s_gp, st);
                }
            }
        }
        int base = (b * BN + p) * 32;
        #pragma unroll
        for (int i = 0; i < 32; i++) g_idx[base + i] = s_ni[i * KT + tid];
    }
}

// ---------------- pass 1: K = exp((dot-1)/eps)*support, + column partial sums ----------------
// 128x128 tile, 256 threads, 8x8 micro-tile. K=64 split into two 32-chunks so
// smem stays static (2 * 32*132 * 4 B = 33.8 KB).
__global__ void pass1_kernel(const float* __restrict__ pc0, const float* __restrict__ pc1,
                             const float* __restrict__ epsp) {
    __shared__ float As[32 * 132];   // [c][row], pad 4
    __shared__ float Bs[32 * 132];
    int b  = blockIdx.z;
    int n0 = blockIdx.y * 128;
    int m0 = blockIdx.x * 128;
    int t  = threadIdx.x;

    int tc = t & 15, tr = t >> 4;     // 16x16 thread grid of 8x8 micro-tiles
    int rb = tr * 8, cb2 = tc * 8;
    float acc[8][8];
    #pragma unroll
    for (int i = 0; i < 8; i++)
        #pragma unroll
        for (int j = 0; j < 8; j++) acc[i][j] = 0.0f;

    int lrow  = t >> 1;               // 0..127
    int lhalf = (t & 1) * 16;         // which 16-channel half of the 32-chunk

    #pragma unroll
    for (int kc = 0; kc < 2; kc++) {
        const float4* srcA = (const float4*)(g_f0n + ((size_t)(b * BN + n0 + lrow)) * 64 + kc * 32 + lhalf);
        const float4* srcB = (const float4*)(g_f1n + ((size_t)(b * BN + m0 + lrow)) * 64 + kc * 32 + lhalf);
        #pragma unroll
        for (int k = 0; k < 4; k++) {
            float4 v = srcA[k];
            int c = lhalf + k * 4;
            As[(c + 0) * 132 + lrow] = v.x; As[(c + 1) * 132 + lrow] = v.y;
            As[(c + 2) * 132 + lrow] = v.z; As[(c + 3) * 132 + lrow] = v.w;
            float4 u = srcB[k];
            Bs[(c + 0) * 132 + lrow] = u.x; Bs[(c + 1) * 132 + lrow] = u.y;
            Bs[(c + 2) * 132 + lrow] = u.z; Bs[(c + 3) * 132 + lrow] = u.w;
        }
        __syncthreads();

        #pragma unroll 4
        for (int c = 0; c < 32; c++) {
            float4 x0 = *(const float4*)&As[c * 132 + rb];
            float4 x1 = *(const float4*)&As[c * 132 + rb + 4];
            float4 y0 = *(const float4*)&Bs[c * 132 + cb2];
            float4 y1 = *(const float4*)&Bs[c * 132 + cb2 + 4];
            float av[8] = {x0.x, x0.y, x0.z, x0.w, x1.x, x1.y, x1.z, x1.w};
            float bv[8] = {y0.x, y0.y, y0.z, y0.w, y1.x, y1.y, y1.z, y1.w};
            #pragma unroll
            for (int i = 0; i < 8; i++)
                #pragma unroll
                for (int j = 0; j < 8; j++) acc[i][j] = fmaf(av[i], bv[j], acc[i][j]);
        }
        __syncthreads();
    }

    float eps = expf(epsp[0]) + 0.025f;
    float inv_eps = 1.0f / eps;

    float p1x[8], p1y[8], p1z[8];
    #pragma unroll
    for (int j = 0; j < 8; j++) {
        int mb_ = (b * BN + m0 + cb2 + j) * 3;
        p1x[j] = pc1[mb_]; p1y[j] = pc1[mb_ + 1]; p1z[j] = pc1[mb_ + 2];
    }

    float colp[8] = {0, 0, 0, 0, 0, 0, 0, 0};
    #pragma unroll
    for (int i = 0; i < 8; i++) {
        int nb_ = (b * BN + n0 + rb + i) * 3;
        float p0x = pc0[nb_], p0y = pc0[nb_ + 1], p0z = pc0[nb_ + 2];
        #pragma unroll
        for (int j = 0; j < 8; j++) {
            float dx = p0x - p1x[j], dy = p0y - p1y[j], dz = p0z - p1z[j];
            float d  = dx * dx + dy * dy + dz * dz;
            float kv = (d < 100.0f) ? fast_exp((acc[i][j] - 1.0f) * inv_eps) : 0.0f;
            acc[i][j] = kv;
            colp[j] += kv;
        }
        size_t off = ((size_t)(b * BN) + n0 + rb + i) * BN + m0 + cb2;
        *(float4*)(g_K + off)     = make_float4(acc[i][0], acc[i][1], acc[i][2], acc[i][3]);
        *(float4*)(g_K + off + 4) = make_float4(acc[i][4], acc[i][5], acc[i][6], acc[i][7]);
    }

    // reduce 16 partial col-sums per column through smem (deterministic)
    #pragma unroll
    for (int j = 0; j < 8; j++) As[tr * 132 + cb2 + j] = colp[j];
    __syncthreads();
    if (t < 128) {
        float s = 0.0f;
        #pragma unroll
        for (int k = 0; k < 16; k++) s += As[k * 132 + t];
        g_colpart[blockIdx.y * (BATCH * BN) + b * BN + m0 + t] = s;
    }
}

// ---------------- b-vector + packed (b, b*pc1) table ----------------
__global__ void bvec_kernel(const float* __restrict__ pc1,
                            const float* __restrict__ gamp, const float* __restrict__ epsp) {
    int t = blockIdx.x * blockDim.x + threadIdx.x;
    if (t >= BATCH * BN) return;
    float cs = 0.0f;
    #pragma unroll 8
    for (int k = 0; k < 32; k++) cs += g_colpart[k * (BATCH * BN) + t];
    float eps = expf(epsp[0]) + 0.025f;
    float gam = expf(gamp[0]);
    float power = gam / (gam + eps);
    float KTa = cs * (1.0f / (float)BN);
    float bv = powf((1.0f / (float)BN) / (KTa + 1e-8f), power);
    float x = pc1[t * 3 + 0], y = pc1[t * 3 + 1], z = pc1[t * 3 + 2];
    g_pb[t] = make_float4(bv, bv * x, bv * y, bv * z);
}

// ---------------- pass 2: row reductions -> ot_flow (one warp per row) ----------------
__global__ void pass2_kernel(const float* __restrict__ pc0,
                             const float* __restrict__ gamp, const float* __restrict__ epsp) {
    int warp = threadIdx.x >> 5, lane = threadIdx.x & 31;
    int b = blockIdx.y;
    int n = blockIdx.x * 8 + warp;
    const float4* Kr = (const float4*)(g_K + ((size_t)(b * BN + n)) * BN);
    const float4* pb = (const float4*)(g_pb + b * BN);
    float sb = 0.f, sx = 0.f, sy = 0.f, sz = 0.f;
    for (int mc = lane; mc < BN / 4; mc += 32) {
        float4 k4 = __ldcs(&Kr[mc]);                  // stream K, don't thrash L1
        float4 q0 = __ldg(&pb[4 * mc + 0]);
        float4 q1 = __ldg(&pb[4 * mc + 1]);
        float4 q2 = __ldg(&pb[4 * mc + 2]);
        float4 q3 = __ldg(&pb[4 * mc + 3]);
        sb = fmaf(k4.x, q0.x, sb); sx = fmaf(k4.x, q0.y, sx); sy = fmaf(k4.x, q0.z, sy); sz = fmaf(k4.x, q0.w, sz);
        sb = fmaf(k4.y, q1.x, sb); sx = fmaf(k4.y, q1.y, sx); sy = fmaf(k4.y, q1.z, sy); sz = fmaf(k4.y, q1.w, sz);
        sb = fmaf(k4.z, q2.x, sb); sx = fmaf(k4.z, q2.y, sx); sy = fmaf(k4.z, q2.z, sy); sz = fmaf(k4.z, q2.w, sz);
        sb = fmaf(k4.w, q3.x, sb); sx = fmaf(k4.w, q3.y, sx); sy = fmaf(k4.w, q3.z, sy); sz = fmaf(k4.w, q3.w, sz);
    }
    #pragma unroll
    for (int o = 16; o; o >>= 1) {
        sb += __shfl_xor_sync(0xffffffffu, sb, o);
        sx += __shfl_xor_sync(0xffffffffu, sx, o);
        sy += __shfl_xor_sync(0xffffffffu, sy, o);
        sz += __shfl_xor_sync(0xffffffffu, sz, o);
    }
    if (lane == 0) {
        float eps = expf(epsp[0]) + 0.025f;
        float gam = expf(gamp[0]);
        float power = gam / (gam + eps);
        float a = powf((1.0f / (float)BN) / (sb + 1e-8f), power);
        float invd = 1.0f / (a * sb + 1e-8f);
        int base = (b * BN + n) * 3;
        g_flow[base + 0] = a * sx * invd - pc0[base + 0];
        g_flow[base + 1] = a * sy * invd - pc0[base + 1];
        g_flow[base + 2] = a * sz * invd - pc0[base + 2];
    }
}

// ---------------- set convolution (block per point, thread per out channel) ----------------
template <int CIN, int COUT>
__global__ void setconv_kernel(const float* __restrict__ fin, const float* __restrict__ pc0,
                               const float* __restrict__ w1, const float* __restrict__ b1,
                               const float* __restrict__ w2, const float* __restrict__ b2,
                               const float* __restrict__ w3, const float* __restrict__ b3,
                               float* __restrict__ fout) {
    __shared__ __align__(16) float sfeat[32 * CIN];
    __shared__ float sedge[32 * 3];
    __shared__ int   sidx[32];
    __shared__ float sh[COUT];
    int pid = blockIdx.x;
    int b = pid >> 12, n = pid & 4095;
    int j = threadIdx.x;
    if (j < 32) sidx[j] = g_idx[pid * 32 + j];
    __syncthreads();
    for (int q = j; q < 32 * CIN; q += COUT) {
        int l = q / CIN, c = q - l * CIN;
        sfeat[q] = fin[((size_t)(b * BN) + sidx[l]) * CIN + c];
    }
    if (j < 32) {
        int m = sidx[j];
        int mb_ = (b * BN + m) * 3, nb_ = (b * BN + n) * 3;
        sedge[j * 3 + 0] = pc0[mb_ + 0] - pc0[nb_ + 0];
        sedge[j * 3 + 1] = pc0[mb_ + 1] - pc0[nb_ + 1];
        sedge[j * 3 + 2] = pc0[mb_ + 2] - pc0[nb_ + 2];
    }
    __syncthreads();

    float w[CIN + 3];
    #pragma unroll
    for (int i = 0; i < CIN + 3; i++) w[i] = w1[i * COUT + j];   // hoisted weight column
    float bias = b1[j];
    float mx = -FLT_MAX;
    for (int l = 0; l < 32; l++) {
        float acc = bias;
        if constexpr (CIN % 4 == 0) {
            const float4* sf4 = (const float4*)&sfeat[l * CIN];
            #pragma unroll
            for (int i = 0; i < CIN / 4; i++) {
                float4 v = sf4[i];
                acc = fmaf(v.x, w[4 * i + 0], acc);
                acc = fmaf(v.y, w[4 * i + 1], acc);
                acc = fmaf(v.z, w[4 * i + 2], acc);
                acc = fmaf(v.w, w[4 * i + 3], acc);
            }
        } else {
            #pragma unroll
            for (int i = 0; i < CIN; i++) acc = fmaf(sfeat[l * CIN + i], w[i], acc);
        }
        acc = fmaf(sedge[l * 3 + 0], w[CIN + 0], acc);
        acc = fmaf(sedge[l * 3 + 1], w[CIN + 1], acc);
        acc = fmaf(sedge[l * 3 + 2], w[CIN + 2], acc);
        mx = fmaxf(mx, lrelu(acc));
    }
    sh[j] = mx;
    __syncthreads();
    float acc2 = b2[j];
    #pragma unroll 4
    for (int i = 0; i < COUT; i++) acc2 = fmaf(sh[i], w2[i * COUT + j], acc2);
    acc2 = lrelu(acc2);
    __syncthreads();
    sh[j] = acc2;
    __syncthreads();
    float acc3 = b3[j];
    #pragma unroll 4
    for (int i = 0; i < COUT; i++) acc3 = fmaf(sh[i], w3[i * COUT + j], acc3);
    fout[(size_t)pid * COUT + j] = lrelu(acc3);
}

// ---------------- final: out = ot_flow + x3 @ wfc + bfc ----------------
__global__ void final_kernel(const float* __restrict__ wfc, const float* __restrict__ bfc,
                             float* __restrict__ out) {
    int t = blockIdx.x * blockDim.x + threadIdx.x;
    if (t >= BATCH * BN * 3) return;
    int pid = t / 3, d = t - pid * 3;
    float acc = bfc[d];
    const float* xr = g_x3 + (size_t)pid * 128;
    #pragma unroll 8
    for (int i = 0; i < 128; i++) acc = fmaf(xr[i], wfc[i * 3 + d], acc);
    out[t] = g_flow[t] + acc;
}

// ---------------- launch ----------------
extern "C" void kernel_launch(void* const* d_in, const int* in_sizes, int n_in,
                              void* d_out, int out_size) {
    const float* pc0     = (const float*)d_in[0];
    const float* pc1     = (const float*)d_in[1];
    const float* feats0  = (const float*)d_in[2];
    const float* feats1  = (const float*)d_in[3];
    const float* gamma   = (const float*)d_in[4];
    const float* epsilon = (const float*)d_in[5];
    const float* w1_1 = (const float*)d_in[6];  const float* b1_1 = (const float*)d_in[7];
    const float* w1_2 = (const float*)d_in[8];  const float* b1_2 = (const float*)d_in[9];
    const float* w1_3 = (const float*)d_in[10]; const float* b1_3 = (const float*)d_in[11];
    const float* w2_1 = (const float*)d_in[12]; const float* b2_1 = (const float*)d_in[13];
    const float* w2_2 = (const float*)d_in[14]; const float* b2_2 = (const float*)d_in[15];
    const float* w2_3 = (const float*)d_in[16]; const float* b2_3 = (const float*)d_in[17];
    const float* w3_1 = (const float*)d_in[18]; const float* b3_1 = (const float*)d_in[19];
    const float* w3_2 = (const float*)d_in[20]; const float* b3_2 = (const float*)d_in[21];
    const float* w3_3 = (const float*)d_in[22]; const float* b3_3 = (const float*)d_in[23];
    const float* wfc  = (const float*)d_in[24]; const float* bfc  = (const float*)d_in[25];
    float* out = (float*)d_out;

    void *p_f0n, *p_f1n, *p_flow, *p_x1, *p_x2, *p_x3;
    cudaGetSymbolAddress(&p_f0n,  g_f0n);
    cudaGetSymbolAddress(&p_f1n,  g_f1n);
    cudaGetSymbolAddress(&p_flow, g_flow);
    cudaGetSymbolAddress(&p_x1,   g_x1);
    cudaGetSymbolAddress(&p_x2,   g_x2);
    cudaGetSymbolAddress(&p_x3,   g_x3);

    norm_kernel<<<1024, 256>>>(feats0, (float*)p_f0n);
    norm_kernel<<<1024, 256>>>(feats1, (float*)p_f1n);
    knn_kernel<<<dim3(BN / (KT / 4), 2), KT>>>(pc0);          // launch #3 (indep of norms)
    pass1_kernel<<<dim3(32, 32, 2), 256>>>(pc0, pc1, epsilon); // launch #4 -> profiled slot
    bvec_kernel<<<32, 256>>>(pc1, gamma, epsilon);
    pass2_kernel<<<dim3(512, 2), 256>>>(pc0, gamma, epsilon);
    setconv_kernel<3, 32><<<BATCH * BN, 32>>>((const float*)p_flow, pc0,
        w1_1, b1_1, w1_2, b1_2, w1_3, b1_3, (float*)p_x1);
    setconv_kernel<32, 64><<<BATCH * BN, 64>>>((const float*)p_x1, pc0,
        w2_1, b2_1, w2_2, b2_2, w2_3, b2_3, (float*)p_x2);
    setconv_kernel<64, 128><<<BATCH * BN, 128>>>((const float*)p_x2, pc0,
        w3_1, b3_1, w3_2, b3_2, w3_3, b3_3, (float*)p_x3);
    final_kernel<<<(BATCH * BN * 3 + 255) / 256, 256>>>(wfc, bfc, out);
}